// round 1
// baseline (speedup 1.0000x reference)
#include <cuda_runtime.h>

#define DT_C 0.02f
#define GRAV_C 10.0f
#define THRUST_C 6.0f
#define TORQUE_C 1.0f

// Batch-invariant PSD matrices, built once per launch by qr_kernel.
__device__ float g_Q[36];
__device__ float g_R[9];

__global__ void qr_kernel(const float* __restrict__ qld, const float* __restrict__ qod,
                          const float* __restrict__ rld, const float* __restrict__ rod) {
    if (threadIdx.x != 0 || blockIdx.x != 0) return;
    // tril_indices(6, -1) row-major order
    const int r6[15] = {1,2,2,3,3,3,4,4,4,4,5,5,5,5,5};
    const int c6[15] = {0,0,1,0,1,2,0,1,2,3,0,1,2,3,4};
    float L[6][6];
    #pragma unroll
    for (int i = 0; i < 6; i++)
        #pragma unroll
        for (int j = 0; j < 6; j++) L[i][j] = 0.0f;
    #pragma unroll
    for (int i = 0; i < 6; i++) L[i][i] = expf(qld[i]);
    #pragma unroll
    for (int t = 0; t < 15; t++) L[r6[t]][c6[t]] = qod[t];
    for (int i = 0; i < 6; i++)
        for (int j = 0; j < 6; j++) {
            float s = 0.0f;
            #pragma unroll
            for (int k = 0; k < 6; k++) s += L[i][k] * L[j][k];
            if (i == j) s += 1e-6f;
            g_Q[i * 6 + j] = s;
        }
    // tril_indices(3, -1): (1,0),(2,0),(2,1)
    const int r3[3] = {1,2,2};
    const int c3[3] = {0,0,1};
    float M[3][3];
    #pragma unroll
    for (int i = 0; i < 3; i++)
        #pragma unroll
        for (int j = 0; j < 3; j++) M[i][j] = 0.0f;
    #pragma unroll
    for (int i = 0; i < 3; i++) M[i][i] = expf(rld[i]);
    #pragma unroll
    for (int t = 0; t < 3; t++) M[r3[t]][c3[t]] = rod[t];
    for (int i = 0; i < 3; i++)
        for (int j = 0; j < 3; j++) {
            float s = 0.0f;
            #pragma unroll
            for (int k = 0; k < 3; k++) s += M[i][k] * M[j][k];
            if (i == j) s += 1e-6f;
            g_R[i * 3 + j] = s;
        }
}

__global__ __launch_bounds__(128)
void ekf_kernel(const float* __restrict__ z, const float* __restrict__ u,
                const float* __restrict__ xprev, const float* __restrict__ Pprev,
                float* __restrict__ out_x, float* __restrict__ out_P, int B) {
    __shared__ float sQ[36];
    __shared__ float sR[9];
    if (threadIdx.x < 36) sQ[threadIdx.x] = g_Q[threadIdx.x];
    if (threadIdx.x < 9)  sR[threadIdx.x] = g_R[threadIdx.x];
    __syncthreads();

    int b = blockIdx.x * blockDim.x + threadIdx.x;
    if (b >= B) return;

    // ---- Load P_prev (36 floats, 9x float4, contiguous per thread) ----
    float Pf[36];
    {
        const float4* p4 = reinterpret_cast<const float4*>(Pprev + (size_t)b * 36);
        #pragma unroll
        for (int i = 0; i < 9; i++) {
            float4 v = p4[i];
            Pf[4 * i + 0] = v.x; Pf[4 * i + 1] = v.y;
            Pf[4 * i + 2] = v.z; Pf[4 * i + 3] = v.w;
        }
    }
#define Pm(i, j) Pf[(i) * 6 + (j)]

    // ---- Load state, control, observation ----
    float px, py, vx, vy, th, om;
    {
        const float2* x2 = reinterpret_cast<const float2*>(xprev + (size_t)b * 6);
        float2 a = x2[0], bb = x2[1], cc = x2[2];
        px = a.x; py = a.y; vx = bb.x; vy = bb.y; th = cc.x; om = cc.y;
    }
    float2 uu = reinterpret_cast<const float2*>(u)[b];
    float z0 = z[(size_t)b * 3 + 0];
    float z1 = z[(size_t)b * 3 + 1];
    float z2 = z[(size_t)b * 3 + 2];

    // ---- Dynamics + Jacobian column-4 coefficients ----
    float mp = fminf(fmaxf(uu.x, 0.0f), 1.0f);
    float s, c;
    __sincosf(th, &s, &c);
    float Tm = THRUST_C * mp;
    float nvx = vx + (-Tm * s) * DT_C;
    float nvy = vy + (Tm * c - GRAV_C) * DT_C;
    float nom = om + (TORQUE_C * uu.y) * DT_C;
    float npx = px + nvx * DT_C;
    float npy = py + nvy * DT_C;
    float nth = th + nom * DT_C;

    float a2 = -Tm * c * DT_C;       // F[2][4]
    float a3 = -Tm * s * DT_C;       // F[3][4]
    float a0 = a2 * DT_C;            // F[0][4]
    float a1 = a3 * DT_C;            // F[1][4]

    // ---- P_pred = F P F^T + Q, F = I + sparse ----
    // Row ops (T = F P). Safe in-place: each row reads only rows with larger index.
    #pragma unroll
    for (int j = 0; j < 6; j++) {
        Pm(0, j) += DT_C * Pm(2, j) + a0 * Pm(4, j);
        Pm(1, j) += DT_C * Pm(3, j) + a1 * Pm(4, j);
        Pm(2, j) += a2 * Pm(4, j);
        Pm(3, j) += a3 * Pm(4, j);
        Pm(4, j) += DT_C * Pm(5, j);
    }
    // Column ops (P_pred = T F^T). Same safety argument on columns.
    #pragma unroll
    for (int i = 0; i < 6; i++) {
        Pm(i, 0) += DT_C * Pm(i, 2) + a0 * Pm(i, 4);
        Pm(i, 1) += DT_C * Pm(i, 3) + a1 * Pm(i, 4);
        Pm(i, 2) += a2 * Pm(i, 4);
        Pm(i, 3) += a3 * Pm(i, 4);
        Pm(i, 4) += DT_C * Pm(i, 5);
    }
    #pragma unroll
    for (int k = 0; k < 36; k++) Pf[k] += sQ[k];

    // ---- S = P_pred[(0,1,4),(0,1,4)] + R; symmetric 3x3 inverse (Cramer) ----
    float S00 = Pm(0, 0) + sR[0];
    float S01 = Pm(0, 1) + sR[1];
    float S02 = Pm(0, 4) + sR[2];
    float S11 = Pm(1, 1) + sR[4];
    float S12 = Pm(1, 4) + sR[5];
    float S22 = Pm(4, 4) + sR[8];

    float c00 = S11 * S22 - S12 * S12;
    float c01 = S02 * S12 - S01 * S22;
    float c02 = S01 * S12 - S02 * S11;
    float c11 = S00 * S22 - S02 * S02;
    float c12 = S01 * S02 - S00 * S12;
    float c22 = S00 * S11 - S01 * S01;
    float invdet = 1.0f / (S00 * c00 + S01 * c01 + S02 * c02);
    float Si[3][3];
    Si[0][0] = c00 * invdet; Si[0][1] = c01 * invdet; Si[0][2] = c02 * invdet;
    Si[1][0] = c01 * invdet; Si[1][1] = c11 * invdet; Si[1][2] = c12 * invdet;
    Si[2][0] = c02 * invdet; Si[2][1] = c12 * invdet; Si[2][2] = c22 * invdet;

    // ---- K = (S^-1 HP)^T : K[k][c] = sum_d HP[d][k] * Si[d][c], HP[d] = row idx_d of P_pred ----
    float K[6][3];
    #pragma unroll
    for (int k = 0; k < 6; k++) {
        float h0 = Pm(0, k), h1 = Pm(1, k), h2 = Pm(4, k);
        #pragma unroll
        for (int cc2 = 0; cc2 < 3; cc2++)
            K[k][cc2] = h0 * Si[0][cc2] + h1 * Si[1][cc2] + h2 * Si[2][cc2];
    }

    // ---- x_upd = x_pred + K y ----
    float y0 = z0 - npx, y1 = z1 - npy, y2 = z2 - nth;
    float xpred[6] = {npx, npy, nvx, nvy, nth, nom};
    float xout[6];
    #pragma unroll
    for (int i = 0; i < 6; i++)
        xout[i] = xpred[i] + K[i][0] * y0 + K[i][1] * y1 + K[i][2] * y2;

    // ---- Joseph form: P_upd = (I-KH) P_pred (I-KH)^T + K R K^T ----
    // A = (I-KH) P_pred : subtract K-weighted rows 0,1,4
    float A[36];
    #pragma unroll
    for (int i = 0; i < 6; i++) {
        #pragma unroll
        for (int k = 0; k < 6; k++) {
            A[i * 6 + k] = Pm(i, k)
                - K[i][0] * Pm(0, k)
                - K[i][1] * Pm(1, k)
                - K[i][2] * Pm(4, k);
        }
    }
    // KR = K @ R
    float KR[6][3];
    #pragma unroll
    for (int i = 0; i < 6; i++) {
        #pragma unroll
        for (int cc2 = 0; cc2 < 3; cc2++)
            KR[i][cc2] = K[i][0] * sR[0 * 3 + cc2]
                       + K[i][1] * sR[1 * 3 + cc2]
                       + K[i][2] * sR[2 * 3 + cc2];
    }
    // P_upd[i][j] = A[i][j] - A[i][{0,1,4}]·K[j] + KR[i]·K[j]
    float Pu[36];
    #pragma unroll
    for (int i = 0; i < 6; i++) {
        float ai0 = A[i * 6 + 0], ai1 = A[i * 6 + 1], ai4 = A[i * 6 + 4];
        #pragma unroll
        for (int j = 0; j < 6; j++) {
            float v = A[i * 6 + j]
                - ai0 * K[j][0] - ai1 * K[j][1] - ai4 * K[j][2]
                + KR[i][0] * K[j][0] + KR[i][1] * K[j][1] + KR[i][2] * K[j][2];
            Pu[i * 6 + j] = v;
        }
    }

    // ---- Stores ----
    {
        float2* ox2 = reinterpret_cast<float2*>(out_x + (size_t)b * 6);
        ox2[0] = make_float2(xout[0], xout[1]);
        ox2[1] = make_float2(xout[2], xout[3]);
        ox2[2] = make_float2(xout[4], xout[5]);
        float4* op4 = reinterpret_cast<float4*>(out_P + (size_t)b * 36);
        #pragma unroll
        for (int i = 0; i < 9; i++)
            op4[i] = make_float4(Pu[4 * i + 0], Pu[4 * i + 1], Pu[4 * i + 2], Pu[4 * i + 3]);
    }
#undef Pm
}

extern "C" void kernel_launch(void* const* d_in, const int* in_sizes, int n_in,
                              void* d_out, int out_size) {
    const float* z   = (const float*)d_in[0];
    const float* u   = (const float*)d_in[1];
    const float* xp  = (const float*)d_in[2];
    const float* Pp  = (const float*)d_in[3];
    const float* qld = (const float*)d_in[4];
    const float* qod = (const float*)d_in[5];
    const float* rld = (const float*)d_in[6];
    const float* rod = (const float*)d_in[7];

    int B = in_sizes[0] / 3;
    float* out_x = (float*)d_out;
    float* out_P = out_x + (size_t)B * 6;

    qr_kernel<<<1, 1>>>(qld, qod, rld, rod);
    ekf_kernel<<<(B + 127) / 128, 128>>>(z, u, xp, Pp, out_x, out_P, B);
}